// round 5
// baseline (speedup 1.0000x reference)
#include <cuda_runtime.h>
#include <cuda_bf16.h>
#include <cstdint>

#define NN 50000      // num nodes
#define EE 800000     // num edges
#define CC 64         // channels (in == out)

// ---------------- scratch (no allocations allowed) ----------------
__device__ __align__(256) int   g_deg[NN];        // degree histogram
__device__ __align__(256) int   g_off[NN + 1];    // CSR row offsets (by target)
__device__ __align__(256) int   g_cursor[NN];     // fill cursors for count-sort
__device__ __align__(256) float g_dis[NN];        // deg^-1/2
__device__ __align__(256) int   g_esrc[EE];       // CSR: src node per (sorted-by-tgt) edge
__device__ __align__(256) float g_agg[NN * CC];   // 12.8 MB aggregate
__device__ int g_is64;                            // 1 if edge_index is int64

// ---------------- kernel 1: zero deg + parallel dtype detect ----------------
__global__ void k_init(const void* __restrict__ edges, int E) {
    int64_t i = (int64_t)blockIdx.x * blockDim.x + threadIdx.x;
    int64_t stride = (int64_t)gridDim.x * blockDim.x;
    for (int64_t k = i; k < NN; k += stride) g_deg[k] = 0;

    // Parallel dtype detection: int64 nonneg < 2^31 => all odd 32-bit words 0.
    // 128 threads each probe one odd word; any nonzero => int32.
    if (blockIdx.x == 0) {
        __shared__ int flag;
        if (threadIdx.x == 0) flag = 0;
        __syncthreads();
        if (threadIdx.x < 128) {
            const unsigned* w = reinterpret_cast<const unsigned*>(edges);
            int64_t pos = 2 * (int64_t)threadIdx.x + 1;
            if (pos < (int64_t)2 * E && w[pos] != 0u) atomicOr(&flag, 1);
        }
        __syncthreads();
        if (threadIdx.x == 0) g_is64 = (flag == 0);
    }
}

__device__ __forceinline__ int load_idx(const void* edges, int64_t pos, int is64) {
    if (is64) return (int)reinterpret_cast<const long long*>(edges)[pos];
    return reinterpret_cast<const int*>(edges)[pos];
}

// ---------------- kernel 2: degree histogram over targets ----------------
__global__ void k_degree(const void* __restrict__ edges, int E) {
    int is64 = g_is64;
    int64_t i = (int64_t)blockIdx.x * blockDim.x + threadIdx.x;
    if (i >= E) return;
    int tgt = load_idx(edges, (int64_t)E + i, is64);
    atomicAdd(&g_deg[tgt], 1);
}

// ---------------- kernel 3: exclusive scan of deg -> off/cursor, + dis ----------------
// Single block, 1024 threads, serial chunks + hierarchical warp scan.
__global__ __launch_bounds__(1024) void k_scan(int n) {
    const int T = 1024;
    int tid  = threadIdx.x;
    int lane = tid & 31;
    int wid  = tid >> 5;
    int chunk = (n + T - 1) / T;
    int lo = tid * chunk;
    int hi = lo + chunk; if (hi > n) hi = n;

    int s = 0;
    for (int i = lo; i < hi; i++) s += g_deg[i];

    // inclusive scan of per-thread sums
    int v = s;
#pragma unroll
    for (int d = 1; d < 32; d <<= 1) {
        int t = __shfl_up_sync(0xffffffffu, v, d);
        if (lane >= d) v += t;
    }
    __shared__ int wsum[32];
    if (lane == 31) wsum[wid] = v;
    __syncthreads();
    if (wid == 0) {
        int w = wsum[lane];
#pragma unroll
        for (int d = 1; d < 32; d <<= 1) {
            int t = __shfl_up_sync(0xffffffffu, w, d);
            if (lane >= d) w += t;
        }
        wsum[lane] = w;
    }
    __syncthreads();

    int base = (v - s) + (wid > 0 ? wsum[wid - 1] : 0);   // exclusive prefix of chunk
    int run = base;
    for (int i = lo; i < hi; i++) {
        int d = g_deg[i];
        g_off[i]    = run;
        g_cursor[i] = run;
        g_dis[i]    = rsqrtf(fmaxf((float)d, 1.0f));
        run += d;
    }
    if (lo < n && hi == n) g_off[n] = run;
}

// ---------------- kernel 4: count-sort edges by target ----------------
__global__ void k_build(const void* __restrict__ edges, int E) {
    int is64 = g_is64;
    int64_t i = (int64_t)blockIdx.x * blockDim.x + threadIdx.x;
    if (i >= E) return;
    int src = load_idx(edges, i, is64);
    int tgt = load_idx(edges, (int64_t)E + i, is64);
    int pos = atomicAdd(&g_cursor[tgt], 1);
    g_esrc[pos] = src;
}

// ---------------- kernel 5: CSR aggregate (no atomics) ----------------
// Half-warp (16 lanes) per target node; each lane owns one float4 (4 channels).
// Accumulate all in-edges in registers, store the agg row once.
__global__ __launch_bounds__(256) void k_agg(const float* __restrict__ x, int n) {
    int t  = blockIdx.x * blockDim.x + threadIdx.x;
    int hw = t >> 4;                 // node id
    int q  = threadIdx.x & 15;       // float4 slot
    if (hw >= n) return;

    int beg = g_off[hw];
    int end = g_off[hw + 1];
    float dt = g_dis[hw];

    const float4* x4 = reinterpret_cast<const float4*>(x);
    float4 acc = make_float4(0.f, 0.f, 0.f, 0.f);

    for (int e = beg; e < end; e++) {
        int src = g_esrc[e];                        // 16-lane broadcast load
        float nm = __ldg(&g_dis[src]) * dt;         // broadcast
        float4 xv = __ldg(&x4[(int64_t)src * 16 + q]);
        acc.x += xv.x * nm;
        acc.y += xv.y * nm;
        acc.z += xv.z * nm;
        acc.w += xv.w * nm;
    }

    reinterpret_cast<float4*>(g_agg)[(int64_t)hw * 16 + q] = acc;
}

// ---------------- kernel 6: out = relu(agg @ W^T + b) ----------------
__global__ __launch_bounds__(256) void k_gemm(const float* __restrict__ W,
                                              const float* __restrict__ b,
                                              float* __restrict__ out, int n) {
    __shared__ float Ws[CC * CC];
    __shared__ float bs[CC];
    for (int i = threadIdx.x; i < CC * CC; i += blockDim.x) Ws[i] = W[i];
    if (threadIdx.x < CC) bs[threadIdx.x] = b[threadIdx.x];
    __syncthreads();

    int node = blockIdx.x * blockDim.x + threadIdx.x;
    if (node >= n) return;

    float4 a[16];
    const float4* arow = reinterpret_cast<const float4*>(g_agg + (int64_t)node * CC);
#pragma unroll
    for (int i = 0; i < 16; i++) a[i] = arow[i];

    float4* orow = reinterpret_cast<float4*>(out + (int64_t)node * CC);
    const float4* Ws4 = reinterpret_cast<const float4*>(Ws);

#pragma unroll
    for (int o = 0; o < CC; o += 4) {
        float acc0 = bs[o + 0], acc1 = bs[o + 1], acc2 = bs[o + 2], acc3 = bs[o + 3];
#pragma unroll
        for (int c = 0; c < 16; c++) {
            float4 av = a[c];
            float4 w0 = Ws4[(o + 0) * 16 + c];
            float4 w1 = Ws4[(o + 1) * 16 + c];
            float4 w2 = Ws4[(o + 2) * 16 + c];
            float4 w3 = Ws4[(o + 3) * 16 + c];
            acc0 += av.x * w0.x + av.y * w0.y + av.z * w0.z + av.w * w0.w;
            acc1 += av.x * w1.x + av.y * w1.y + av.z * w1.z + av.w * w1.w;
            acc2 += av.x * w2.x + av.y * w2.y + av.z * w2.z + av.w * w2.w;
            acc3 += av.x * w3.x + av.y * w3.y + av.z * w3.z + av.w * w3.w;
        }
        float4 r;
        r.x = fmaxf(acc0, 0.f);
        r.y = fmaxf(acc1, 0.f);
        r.z = fmaxf(acc2, 0.f);
        r.w = fmaxf(acc3, 0.f);
        orow[o >> 2] = r;
    }
}

// ---------------- launch ----------------
extern "C" void kernel_launch(void* const* d_in, const int* in_sizes, int n_in,
                              void* d_out, int out_size) {
    const float* x     = (const float*)d_in[0];
    const void*  edges = d_in[1];                 // int32 or int64, runtime-detected
    const float* W     = (const float*)d_in[2];
    const float* b     = (const float*)d_in[3];
    float* out = (float*)d_out;

    const int n = in_sizes[0] / CC;               // 50000
    const int E = in_sizes[1] / 2;                // 800000

    k_init<<<(NN + 255) / 256, 256>>>(edges, E);
    k_degree<<<(E + 255) / 256, 256>>>(edges, E);
    k_scan<<<1, 1024>>>(n);
    k_build<<<(E + 255) / 256, 256>>>(edges, E);
    {
        int64_t threads = (int64_t)n * 16;
        int blocks = (int)((threads + 255) / 256);
        k_agg<<<blocks, 256>>>(x, n);
    }
    k_gemm<<<(n + 255) / 256, 256>>>(W, b, out, n);
}

// round 6
// speedup vs baseline: 3.9550x; 3.9550x over previous
#include <cuda_runtime.h>
#include <cuda_bf16.h>
#include <cstdint>

#define NN  50000     // num nodes
#define EE  800000    // num edges
#define CC  64        // channels (in == out)
#define CAP 96        // per-node slot capacity (Poisson(16): P(deg>96) ~ 1e-50)
#define OVF_MAX 8192  // overflow edge buffer (correctness fallback)

// ---------------- scratch (no allocations allowed) ----------------
__device__ __align__(256) int   g_cnt[NN];          // degree / fill cursor
__device__ __align__(256) float g_dis[NN];          // clip(deg,1)^-1/2
__device__ __align__(256) int   g_slot[NN * CAP];   // src lists per target (19.2 MB)
__device__ __align__(256) int   g_ovf[OVF_MAX * 2]; // overflow (src,tgt) pairs
__device__ __align__(256) float g_agg[NN * CC];     // 12.8 MB aggregate
__device__ int g_novf;                              // overflow count
__device__ int g_is64;                              // 1 if edge_index is int64

// ---------------- kernel 1: zero counters + parallel dtype detect ----------------
__global__ void k_init(const void* __restrict__ edges, int E) {
    int i = blockIdx.x * blockDim.x + threadIdx.x;
    int stride = gridDim.x * blockDim.x;
    for (int k = i; k < NN; k += stride) g_cnt[k] = 0;
    if (i == 0) g_novf = 0;

    // int64 nonneg < 2^31  =>  every odd 32-bit word is zero.
    // 128 threads probe one odd word each; any nonzero => int32.
    if (blockIdx.x == 0) {
        __shared__ int flag;
        if (threadIdx.x == 0) flag = 0;
        __syncthreads();
        if (threadIdx.x < 128) {
            const unsigned* w = reinterpret_cast<const unsigned*>(edges);
            int64_t pos = 2 * (int64_t)threadIdx.x + 1;
            if (pos < (int64_t)2 * E && w[pos] != 0u) atomicOr(&flag, 1);
        }
        __syncthreads();
        if (threadIdx.x == 0) g_is64 = (flag == 0);
    }
}

__device__ __forceinline__ int load_idx(const void* edges, int64_t pos, int is64) {
    if (is64) return (int)reinterpret_cast<const long long*>(edges)[pos];
    return reinterpret_cast<const int*>(edges)[pos];
}

// ---------------- kernel 2: fill slot table (count-sort, no scan) ----------------
__global__ void k_fill(const void* __restrict__ edges, int E) {
    int is64 = g_is64;
    int64_t i = (int64_t)blockIdx.x * blockDim.x + threadIdx.x;
    if (i >= E) return;
    int src = load_idx(edges, i, is64);
    int tgt = load_idx(edges, (int64_t)E + i, is64);
    int pos = atomicAdd(&g_cnt[tgt], 1);
    if (pos < CAP) {
        g_slot[(int64_t)tgt * CAP + pos] = src;
    } else {
        int o = atomicAdd(&g_novf, 1);
        if (o < OVF_MAX) { g_ovf[2 * o] = src; g_ovf[2 * o + 1] = tgt; }
    }
}

// ---------------- kernel 3: deg_inv_sqrt ----------------
__global__ void k_dis(int n) {
    int i = blockIdx.x * blockDim.x + threadIdx.x;
    if (i >= n) return;
    g_dis[i] = rsqrtf(fmaxf((float)g_cnt[i], 1.0f));
}

// ---------------- kernel 4: gather-aggregate, no atomics ----------------
// Half-warp (16 lanes) per target node; lane q owns float4 channel slot q.
// 4-wide unroll => 4 independent src->x load chains in flight.
__global__ __launch_bounds__(256) void k_agg(const float* __restrict__ x, int n) {
    int t  = blockIdx.x * blockDim.x + threadIdx.x;
    int nd = t >> 4;                  // node id
    int q  = threadIdx.x & 15;        // float4 slot in row
    if (nd >= n) return;

    int deg = g_cnt[nd];
    int d   = deg < CAP ? deg : CAP;
    float dt = g_dis[nd];
    const int* slots = g_slot + (int64_t)nd * CAP;
    const float4* x4 = reinterpret_cast<const float4*>(x);

    float4 acc = make_float4(0.f, 0.f, 0.f, 0.f);
    int e = 0;
    for (; e + 4 <= d; e += 4) {
        int s0 = slots[e + 0], s1 = slots[e + 1], s2 = slots[e + 2], s3 = slots[e + 3];
        float n0 = __ldg(&g_dis[s0]) * dt;
        float n1 = __ldg(&g_dis[s1]) * dt;
        float n2 = __ldg(&g_dis[s2]) * dt;
        float n3 = __ldg(&g_dis[s3]) * dt;
        float4 v0 = __ldg(&x4[(int64_t)s0 * 16 + q]);
        float4 v1 = __ldg(&x4[(int64_t)s1 * 16 + q]);
        float4 v2 = __ldg(&x4[(int64_t)s2 * 16 + q]);
        float4 v3 = __ldg(&x4[(int64_t)s3 * 16 + q]);
        acc.x += v0.x * n0 + v1.x * n1 + v2.x * n2 + v3.x * n3;
        acc.y += v0.y * n0 + v1.y * n1 + v2.y * n2 + v3.y * n3;
        acc.z += v0.z * n0 + v1.z * n1 + v2.z * n2 + v3.z * n3;
        acc.w += v0.w * n0 + v1.w * n1 + v2.w * n2 + v3.w * n3;
    }
    for (; e < d; e++) {
        int s = slots[e];
        float nm = __ldg(&g_dis[s]) * dt;
        float4 v = __ldg(&x4[(int64_t)s * 16 + q]);
        acc.x += v.x * nm; acc.y += v.y * nm; acc.z += v.z * nm; acc.w += v.w * nm;
    }

    reinterpret_cast<float4*>(g_agg)[(int64_t)nd * 16 + q] = acc;
}

// ---------------- kernel 5: overflow edges via RED atomics (rarely any) ----------------
__global__ void k_ovf(const float* __restrict__ x) {
    int novf = g_novf;
    int ne = novf < OVF_MAX ? novf : OVF_MAX;
    int t = blockIdx.x * blockDim.x + threadIdx.x;
    int e = t >> 4;
    int q = threadIdx.x & 15;
    if (e >= ne) return;
    int src = g_ovf[2 * e], tgt = g_ovf[2 * e + 1];
    float nm = g_dis[src] * g_dis[tgt];
    const float4* x4 = reinterpret_cast<const float4*>(x);
    float4 v = __ldg(&x4[(int64_t)src * 16 + q]);
    float* dst = g_agg + ((int64_t)tgt * CC + q * 4);
    asm volatile("red.global.add.v4.f32 [%0], {%1, %2, %3, %4};"
                 :: "l"(dst), "f"(v.x * nm), "f"(v.y * nm), "f"(v.z * nm), "f"(v.w * nm)
                 : "memory");
}

// ---------------- kernel 6: out = relu(agg @ W^T + b) ----------------
__global__ __launch_bounds__(256) void k_gemm(const float* __restrict__ W,
                                              const float* __restrict__ b,
                                              float* __restrict__ out, int n) {
    __shared__ float Ws[CC * CC];
    __shared__ float bs[CC];
    for (int i = threadIdx.x; i < CC * CC; i += blockDim.x) Ws[i] = W[i];
    if (threadIdx.x < CC) bs[threadIdx.x] = b[threadIdx.x];
    __syncthreads();

    int node = blockIdx.x * blockDim.x + threadIdx.x;
    if (node >= n) return;

    float4 a[16];
    const float4* arow = reinterpret_cast<const float4*>(g_agg + (int64_t)node * CC);
#pragma unroll
    for (int i = 0; i < 16; i++) a[i] = arow[i];

    float4* orow = reinterpret_cast<float4*>(out + (int64_t)node * CC);
    const float4* Ws4 = reinterpret_cast<const float4*>(Ws);

#pragma unroll
    for (int o = 0; o < CC; o += 4) {
        float acc0 = bs[o + 0], acc1 = bs[o + 1], acc2 = bs[o + 2], acc3 = bs[o + 3];
#pragma unroll
        for (int c = 0; c < 16; c++) {
            float4 av = a[c];
            float4 w0 = Ws4[(o + 0) * 16 + c];
            float4 w1 = Ws4[(o + 1) * 16 + c];
            float4 w2 = Ws4[(o + 2) * 16 + c];
            float4 w3 = Ws4[(o + 3) * 16 + c];
            acc0 += av.x * w0.x + av.y * w0.y + av.z * w0.z + av.w * w0.w;
            acc1 += av.x * w1.x + av.y * w1.y + av.z * w1.z + av.w * w1.w;
            acc2 += av.x * w2.x + av.y * w2.y + av.z * w2.z + av.w * w2.w;
            acc3 += av.x * w3.x + av.y * w3.y + av.z * w3.z + av.w * w3.w;
        }
        float4 r;
        r.x = fmaxf(acc0, 0.f);
        r.y = fmaxf(acc1, 0.f);
        r.z = fmaxf(acc2, 0.f);
        r.w = fmaxf(acc3, 0.f);
        orow[o >> 2] = r;
    }
}

// ---------------- launch ----------------
extern "C" void kernel_launch(void* const* d_in, const int* in_sizes, int n_in,
                              void* d_out, int out_size) {
    const float* x     = (const float*)d_in[0];
    const void*  edges = d_in[1];                 // int32 or int64, runtime-detected
    const float* W     = (const float*)d_in[2];
    const float* b     = (const float*)d_in[3];
    float* out = (float*)d_out;

    const int n = in_sizes[0] / CC;               // 50000
    const int E = in_sizes[1] / 2;                // 800000

    k_init<<<(NN + 255) / 256, 256>>>(edges, E);
    k_fill<<<(E + 255) / 256, 256>>>(edges, E);
    k_dis<<<(n + 255) / 256, 256>>>(n);
    {
        int64_t threads = (int64_t)n * 16;
        int blocks = (int)((threads + 255) / 256);
        k_agg<<<blocks, 256>>>(x, n);
    }
    k_ovf<<<(OVF_MAX * 16 + 255) / 256, 256>>>(x);
    k_gemm<<<(n + 255) / 256, 256>>>(W, b, out, n);
}